// round 1
// baseline (speedup 1.0000x reference)
#include <cuda_runtime.h>

// SampleQueryExtractionLayer: bilinear-style 4-tap gather.
// features: [B=4, N=4096, C=256] fp32   (d_in[0])
// query_points: [B=4, S=8, Q=256, 2] fp32 (d_in[1]) -> 8192 points
// out: [B, S, Q, C] fp32 = [8192, 256]
//
// mask = relu(1 - L1(p, grid) + eps)^2, normalized over grid; only the 4
// corners of the containing unit cell have non-negligible weight (all other
// lattice points contribute <= eps^2 = 1e-8, ignorable at rel_err 1e-3).

#define EPS_F 0.0001f

__global__ __launch_bounds__(256, 4)
void sqe_kernel(const float* __restrict__ feat,
                const float* __restrict__ qp,
                float* __restrict__ out)
{
    const int tid = threadIdx.x;
    const int g   = blockIdx.x * 4 + (tid >> 6);   // global query id, 0..8191
    const int c4  = (tid & 63);                    // float4 lane within channel dim

    // Load query point (y, x). 64 threads hit the same 8B -> broadcast.
    const float2 p = __ldg(((const float2*)qp) + g);
    const float py = p.x;   // coordinate 0 compares against yy (row)
    const float px = p.y;   // coordinate 1 compares against xx (col)

    const float y0f = floorf(py);
    const float x0f = floorf(px);
    const float dy = py - y0f;
    const float dx = px - x0f;
    const int y0 = (int)y0f;
    const int x0 = (int)x0f;

    // L1 distances to the 4 cell corners
    const float m00 = fmaxf(0.0f, 1.0f - (dy + dx)               + EPS_F);
    const float m01 = fmaxf(0.0f, 1.0f - (dy + (1.0f - dx))      + EPS_F);
    const float m10 = fmaxf(0.0f, 1.0f - ((1.0f - dy) + dx)      + EPS_F);
    const float m11 = fmaxf(0.0f, 1.0f - ((2.0f - dy) - dx)      + EPS_F);

    float w00 = m00 * m00;
    float w01 = m01 * m01;
    float w10 = m10 * m10;
    float w11 = m11 * m11;
    const float inv = 1.0f / (w00 + w01 + w10 + w11 + EPS_F);
    w00 *= inv; w01 *= inv; w10 *= inv; w11 *= inv;

    // Gather 4 feature rows. b = g / 2048 (S*Q = 2048 queries per batch).
    const int b = g >> 11;
    const int n00 = y0 * 64 + x0;                      // (y0, x0)
    const float4* fb = (const float4*)(feat + (size_t)b * (4096u * 256u));
    const float4* r00 = fb + (size_t)n00 * 64 + c4;    // row stride = 64 float4
    const float4* r01 = r00 + 64;                      // (y0, x0+1)
    const float4* r10 = r00 + 64 * 64;                 // (y0+1, x0)
    const float4* r11 = r10 + 64;                      // (y0+1, x0+1)

    const float4 f00 = __ldg(r00);
    const float4 f01 = __ldg(r01);
    const float4 f10 = __ldg(r10);
    const float4 f11 = __ldg(r11);

    float4 acc;
    acc.x = w00 * f00.x + w01 * f01.x + w10 * f10.x + w11 * f11.x;
    acc.y = w00 * f00.y + w01 * f01.y + w10 * f10.y + w11 * f11.y;
    acc.z = w00 * f00.z + w01 * f01.z + w10 * f10.z + w11 * f11.z;
    acc.w = w00 * f00.w + w01 * f01.w + w10 * f10.w + w11 * f11.w;

    ((float4*)out)[(size_t)g * 64 + c4] = acc;
}

extern "C" void kernel_launch(void* const* d_in, const int* in_sizes, int n_in,
                              void* d_out, int out_size)
{
    (void)in_sizes; (void)n_in; (void)out_size;
    const float* feat = (const float*)d_in[0];
    const float* qp   = (const float*)d_in[1];
    float* out        = (float*)d_out;

    // 8192 queries, 4 queries per 256-thread block -> 2048 blocks
    sqe_kernel<<<2048, 256>>>(feat, qp, out);
}